// round 6
// baseline (speedup 1.0000x reference)
#include <cuda_runtime.h>
#include <cstdint>
#include <cstddef>

// ============================================================================
// W8A8B8O8 Linear, sm_103 base ISA (tcgen05 locked out: harness PTX target has
// no 'a' suffix).  out[8192,4096] = sat_rne((x_i8 @ W_i8) * (a*b)); harness
// promotes int8 tensors to 32-bit buffers, output read as float32.
//
// Launch 1: w_convert_transpose  w[K,N] 32-bit -> g_wT[N,K] int8.
// Launch 2: fused GEMM — A converted in-kernel from x (32-bit) with a 2-buffer
//           LDG->convert->STS path; B via 4-stage cp.async from g_wT.
//           mma.sync m16n8k32 s8, BM=128 BN=256 BK=64, 512 threads / 16 warps
//           (warp tile 64x32) for 4 warps/SMSP latency hiding.
// ============================================================================

#define DINLINE __device__ __forceinline__

static constexpr int M_TOTAL = 8192;
static constexpr int K_TOTAL = 4096;
static constexpr int N_TOTAL = 4096;

static constexpr int BM = 128;
static constexpr int BN = 256;
static constexpr int BK = 64;
static constexpr int BSTAGES = 4;                 // cp.async stages for B
static constexpr int KCHUNKS = K_TOTAL / BK;      // 64
static constexpr int NUM_M = M_TOTAL / BM;        // 64
static constexpr int NUM_N = N_TOTAL / BN;        // 16
static constexpr int GROUP_M = 8;
static constexpr int NTHREADS = 512;              // 16 warps (2x8), warp tile 64x32

static constexpr uint32_t A_STAGE = BM * BK;                  // 8 KB
static constexpr uint32_t B_STAGE = BN * BK;                  // 16 KB
static constexpr uint32_t SM_B = 2 * A_STAGE;                 // A double-buffer first
static constexpr uint32_t SMEM_TOTAL = SM_B + BSTAGES * B_STAGE;  // 80 KB

// Transposed int8 weight scratch — static __device__ global, no allocation.
__device__ uint8_t g_wT[(size_t)N_TOTAL * K_TOTAL];   // 16 MB

// Packed-tile offset: 2 logical rows per 128B smem row; 16B granule index is
// xor-swizzled with the low 3 bits of the smem row.
DINLINE uint32_t swz_addr(uint32_t row128, uint32_t gran) {
    return row128 * 128u + ((gran ^ (row128 & 7u)) << 4);
}

DINLINE uint32_t smem_u32(const void* p) {
    uint32_t r;
    asm("{ .reg .u64 t; cvta.to.shared.u64 t, %1; cvt.u32.u64 %0, t; }" : "=r"(r) : "l"(p));
    return r;
}

DINLINE void cp_async16(uint32_t saddr, const void* gaddr) {
    asm volatile("cp.async.cg.shared.global [%0], [%1], 16;" :: "r"(saddr), "l"(gaddr) : "memory");
}
DINLINE void cp_commit() { asm volatile("cp.async.commit_group;" ::: "memory"); }
DINLINE void cp_wait2() { asm volatile("cp.async.wait_group 2;" ::: "memory"); }

#define LDSM4(r, addr)                                                         \
    asm volatile("ldmatrix.sync.aligned.m8n8.x4.shared.b16 {%0,%1,%2,%3}, [%4];" \
                 : "=r"((r)[0]), "=r"((r)[1]), "=r"((r)[2]), "=r"((r)[3])      \
                 : "r"(addr))

DINLINE void mma_s8(uint32_t* c, const uint32_t* a, uint32_t b0, uint32_t b1) {
    asm volatile(
        "mma.sync.aligned.m16n8k32.row.col.s32.s8.s8.s32 "
        "{%0,%1,%2,%3}, {%4,%5,%6,%7}, {%8,%9}, {%0,%1,%2,%3};"
        : "+r"(c[0]), "+r"(c[1]), "+r"(c[2]), "+r"(c[3])
        : "r"(a[0]), "r"(a[1]), "r"(a[2]), "r"(a[3]), "r"(b0), "r"(b1));
}

DINLINE int q8(int v, float s) {
    int q = __float2int_rn((float)v * s);   // RNE matches jnp.round
    return q < -128 ? -128 : (q > 127 ? 127 : q);
}

// Auto-detect element storage: small int bit-pattern => int32 storage; else
// interpret the bits as float32 and round-to-nearest-even. (Exact for the
// integral values this problem carries; 0 agrees under both readings.)
DINLINE uint32_t cvt_b(uint32_t bits) {
    int v = (int)bits;
    if (v < -128 || v > 127) v = __float2int_rn(__int_as_float(bits));
    v = v < -128 ? -128 : (v > 127 ? 127 : v);
    return (uint32_t)v & 0xFFu;
}

// ============================================================================
// Weight convert + transpose: w[K,N] (N-contig, 32-bit stored) -> g_wT[N,K] int8
// ============================================================================
__global__ void __launch_bounds__(256) w_convert_transpose(const uint32_t* __restrict__ w) {
    __shared__ uint8_t t[64][65];
    const int tid = threadIdx.x;
    const int n0 = blockIdx.x * 64;
    const int k0 = blockIdx.y * 64;

    const int r = tid >> 2;             // k-row within tile
    const int cseg = (tid & 3) * 16;    // n-col segment
    const uint32_t* src = w + (size_t)(k0 + r) * N_TOTAL + n0 + cseg;
#pragma unroll
    for (int i = 0; i < 16; i += 4) {
        const uint4 v = *reinterpret_cast<const uint4*>(src + i);
        t[r][cseg + i + 0] = (uint8_t)cvt_b(v.x);
        t[r][cseg + i + 1] = (uint8_t)cvt_b(v.y);
        t[r][cseg + i + 2] = (uint8_t)cvt_b(v.z);
        t[r][cseg + i + 3] = (uint8_t)cvt_b(v.w);
    }
    __syncthreads();

    const int n = tid >> 2;             // n-row of output
    const int kseg = (tid & 3) * 16;    // k segment
    alignas(16) uint8_t o[16];
#pragma unroll
    for (int j = 0; j < 16; ++j) o[j] = t[kseg + j][n];
    *reinterpret_cast<uint4*>(g_wT + (size_t)(n0 + n) * K_TOTAL + k0 + kseg) =
        *reinterpret_cast<const uint4*>(o);
}

// ============================================================================
// Fused GEMM kernel (A converted in-kernel)
// ============================================================================
__global__ void __launch_bounds__(NTHREADS, 1)
w8a8_gemm_kernel(const uint32_t* __restrict__ x,
                 const float* __restrict__ ascale,
                 const float* __restrict__ bscale,
                 float* __restrict__ out) {
    extern __shared__ __align__(1024) uint8_t smem_raw[];
    const uint32_t smem = smem_u32(smem_raw);
    const int t = threadIdx.x;
    const int lane = t & 31;
    const int warp = t >> 5;
    const int wm = warp >> 3;   // 0..1  (64 rows each)
    const int wn = warp & 7;    // 0..7  (32 cols each)

    // --- M-grouped raster: W tiles stay L2-resident while A streams ---
    const int bid = blockIdx.x;
    const int group_sz = GROUP_M * NUM_N;
    const int gid = bid / group_sz;
    const int within = bid - gid * group_sz;
    const int pid_m = gid * GROUP_M + (within % GROUP_M);
    const int pid_n = within / GROUP_M;
    const int m0 = pid_m * BM;
    const int n0 = pid_n * BN;

    // --- A producer: one 16B output granule per thread per chunk ---
    const int am_p = t >> 2;            // 0..127
    const int ak16_p = t & 3;           // 0..3
    const uint32_t aSoff = swz_addr(am_p >> 1, (am_p & 1) * 4 + ak16_p);
    const uint32_t* aGp = x + (size_t)(m0 + am_p) * K_TOTAL + ak16_p * 16;

    // --- B producer: two 16B granules per thread per stage ---
    uint32_t bS[2]; const uint8_t* bG[2];
#pragma unroll
    for (int i = 0; i < 2; ++i) {
        const int q = t + i * NTHREADS;            // 0..1023
        const int n = q >> 2, k16 = q & 3;
        bS[i] = smem + SM_B + swz_addr(n >> 1, (n & 1) * 4 + k16);
        bG[i] = g_wT + (size_t)(n0 + n) * K_TOTAL + k16 * 16;
    }

    auto load_b_stage = [&](int s, int chunk) {
        const uint32_t so = s * B_STAGE;
        const size_t ko = (size_t)chunk * BK;
#pragma unroll
        for (int i = 0; i < 2; ++i) cp_async16(bS[i] + so, bG[i] + ko);
    };

    auto store_a = [&](int buf, const uint4* af) {
        uint4 p;
        p.x = cvt_b(af[0].x) | (cvt_b(af[0].y) << 8) | (cvt_b(af[0].z) << 16) | (cvt_b(af[0].w) << 24);
        p.y = cvt_b(af[1].x) | (cvt_b(af[1].y) << 8) | (cvt_b(af[1].z) << 16) | (cvt_b(af[1].w) << 24);
        p.z = cvt_b(af[2].x) | (cvt_b(af[2].y) << 8) | (cvt_b(af[2].z) << 16) | (cvt_b(af[2].w) << 24);
        p.w = cvt_b(af[3].x) | (cvt_b(af[3].y) << 8) | (cvt_b(af[3].z) << 16) | (cvt_b(af[3].w) << 24);
        *reinterpret_cast<uint4*>(smem_raw + buf * A_STAGE + aSoff) = p;
    };

    // --- consumer ldmatrix lane base OFFSETS ---
    // A x4 (PTX ISA a0..a3): m0 = rows 0-7 k[0:16), m1 = rows 8-15 k[0:16),
    //                        m2 = rows 0-7 k[16:32), m3 = rows 8-15 k[16:32)
    uint32_t aOff, bOff;
    {
        const int mlocal = ((lane >> 3) & 1) * 8 + (lane & 7);
        const int k16a = lane >> 4;
        const int am = wm * 64 + mlocal;
        aOff = swz_addr(am >> 1, (am & 1) * 4 + k16a);
        // B x4: m0 = cols 0-7 k[0:16), m1 = cols 0-7 k[16:32),
        //       m2 = cols 8-15 k[0:16), m3 = cols 8-15 k[16:32)
        const int j = lane >> 3;
        const int nlocal = (j >> 1) * 8 + (lane & 7);
        const int k16b = j & 1;
        const int bn = wn * 32 + nlocal;
        bOff = SM_B + swz_addr(bn >> 1, (bn & 1) * 4 + k16b);
    }

    uint32_t acc[4][4][4];
#pragma unroll
    for (int mt = 0; mt < 4; ++mt)
#pragma unroll
        for (int nt = 0; nt < 4; ++nt)
#pragma unroll
            for (int r = 0; r < 4; ++r) acc[mt][nt][r] = 0;

    // --- prologue: A chunk 0 -> buffer 0; B chunks 0..2 via cp.async ---
    {
        uint4 af[4];
#pragma unroll
        for (int i = 0; i < 4; ++i) af[i] = *reinterpret_cast<const uint4*>(aGp + i * 4);
        store_a(0, af);
    }
#pragma unroll
    for (int s = 0; s < BSTAGES - 1; ++s) { load_b_stage(s, s); cp_commit(); }

    // --- main loop ---
    for (int c = 0; c < KCHUNKS; ++c) {
        cp_wait2();
        __syncthreads();

        // A global loads for chunk c+1 (held in regs across the MMA body)
        uint4 af[4];
        const bool havA = (c + 1) < KCHUNKS;
        if (havA) {
            const uint32_t* ap = aGp + (size_t)(c + 1) * BK;
#pragma unroll
            for (int i = 0; i < 4; ++i) af[i] = *reinterpret_cast<const uint4*>(ap + i * 4);
        }
        // B prefetch for chunk c+3
        if (c + BSTAGES - 1 < KCHUNKS) load_b_stage((c + BSTAGES - 1) & (BSTAGES - 1), c + BSTAGES - 1);
        cp_commit();

        const uint32_t aso = (uint32_t)(c & 1) * A_STAGE;
        const uint32_t bso = (uint32_t)(c & (BSTAGES - 1)) * B_STAGE;
#pragma unroll
        for (int kp = 0; kp < 2; ++kp) {
            const uint32_t kx = (uint32_t)kp << 5;
            uint32_t av[4][4];
#pragma unroll
            for (int mt = 0; mt < 4; ++mt) {
                const uint32_t ad = smem + ((aOff + aso + mt * 1024u) ^ kx);
                LDSM4(av[mt], ad);
            }
            uint32_t bv[2][4];
#pragma unroll
            for (int nt2 = 0; nt2 < 2; ++nt2) {
                const uint32_t bd = smem + ((bOff + bso + nt2 * 1024u) ^ kx);
                LDSM4(bv[nt2], bd);
            }
#pragma unroll
            for (int mt = 0; mt < 4; ++mt)
#pragma unroll
                for (int nt = 0; nt < 4; ++nt) {
                    const uint32_t* bp = &bv[nt >> 1][(nt & 1) * 2];
                    mma_s8(acc[mt][nt], av[mt], bp[0], bp[1]);
                }
        }

        // A convert + store for chunk c+1 (visible after next barrier)
        if (havA) store_a((c + 1) & 1, af);
    }

    // --- epilogue: quantize (RNE + clamp) and store float32 ---
    const float scl = ascale[0] * bscale[0];
#pragma unroll
    for (int mt = 0; mt < 4; ++mt) {
#pragma unroll
        for (int nt = 0; nt < 4; ++nt) {
            const int row = m0 + wm * 64 + mt * 16 + (lane >> 2);
            const int col = n0 + wn * 32 + nt * 8 + 2 * (lane & 3);
            const int* a4 = reinterpret_cast<const int*>(acc[mt][nt]);
            float2 v0, v1;
            v0.x = (float)q8(a4[0], scl);
            v0.y = (float)q8(a4[1], scl);
            v1.x = (float)q8(a4[2], scl);
            v1.y = (float)q8(a4[3], scl);
            *reinterpret_cast<float2*>(out + (size_t)row * N_TOTAL + col) = v0;
            *reinterpret_cast<float2*>(out + (size_t)(row + 8) * N_TOTAL + col) = v1;
        }
    }
}

// ============================================================================
// Launch — identify inputs by element count (robust to metadata ordering):
//   x: 8192*4096 = 33554432   weight: 4096*4096 = 16777216   a, b: 1 each
// ============================================================================
extern "C" void kernel_launch(void* const* d_in, const int* in_sizes, int n_in,
                              void* d_out, int out_size) {
    (void)out_size;
    const uint32_t* x = nullptr;
    const uint32_t* w = nullptr;
    const float* s1 = nullptr;
    const float* s2 = nullptr;
    for (int i = 0; i < n_in; ++i) {
        const long sz = in_sizes[i];
        if (sz == (long)M_TOTAL * K_TOTAL) x = (const uint32_t*)d_in[i];
        else if (sz == (long)K_TOTAL * N_TOTAL) w = (const uint32_t*)d_in[i];
        else if (sz == 1) { if (!s1) s1 = (const float*)d_in[i]; else s2 = (const float*)d_in[i]; }
    }
    if (!x || !w || !s1 || !s2) return;

    cudaFuncSetAttribute(w8a8_gemm_kernel,
                         cudaFuncAttributeMaxDynamicSharedMemorySize, (int)SMEM_TOTAL);

    w_convert_transpose<<<dim3(N_TOTAL / 64, K_TOTAL / 64), 256>>>(w);
    w8a8_gemm_kernel<<<NUM_M * NUM_N, NTHREADS, SMEM_TOTAL>>>(x, s1, s2, (float*)d_out);
}

// round 7
// speedup vs baseline: 1.5464x; 1.5464x over previous
#include <cuda_runtime.h>
#include <cstdint>
#include <cstddef>

// ============================================================================
// W8A8B8O8 Linear, sm_103 base ISA. Legacy mma.sync IMMA is emulated at ~55
// cyc/instr/SMSP (measured: tensor pipe 82.6% at 2.1ms) => all-tensor ceiling
// ~1.75ms. This version runs TWO engines concurrently per CTA:
//   - 8 tensor warps:  cols [0,160)  via mma.sync m16n8k32 s8 (warp tile 64x40)
//   - 8 dp4a  warps:   cols [160,256) via IDP4A on the fma/alu pipes
// Both consume the same 4-stage cp.async SMEM pipeline (BM=128, BN=256, BK=64).
// x/w are 32-bit promoted int8; converted to packed int8 scratch first.
// ============================================================================

#define DINLINE __device__ __forceinline__

static constexpr int M_TOTAL = 8192;
static constexpr int K_TOTAL = 4096;
static constexpr int N_TOTAL = 4096;

static constexpr int BM = 128;
static constexpr int BN = 256;
static constexpr int BK = 64;
static constexpr int STAGES = 4;
static constexpr int KCHUNKS = K_TOTAL / BK;      // 64
static constexpr int NUM_M = M_TOTAL / BM;        // 64
static constexpr int NUM_N = N_TOTAL / BN;        // 16
static constexpr int GROUP_M = 8;
static constexpr int NTHREADS = 512;              // 8 tensor warps + 8 dp4a warps
static constexpr int TENSOR_N = 160;              // tensor cols per CTA tile

static constexpr uint32_t A_BYTES = BM * BK;                  // 8 KB
static constexpr uint32_t B_BYTES = BN * BK;                  // 16 KB
static constexpr uint32_t STAGE_BYTES = A_BYTES + B_BYTES;    // 24 KB
static constexpr uint32_t SMEM_TOTAL = STAGES * STAGE_BYTES;  // 96 KB

// int8 scratch — static __device__ globals, no allocation.
__device__ uint8_t g_x8[(size_t)M_TOTAL * K_TOTAL];   // 32 MB
__device__ uint8_t g_wT[(size_t)N_TOTAL * K_TOTAL];   // 16 MB

// Packed-tile offset: 2 logical rows per 128B smem row; 16B granule index is
// xor-swizzled with the low 3 bits of the smem row.
DINLINE uint32_t swz_addr(uint32_t row128, uint32_t gran) {
    return row128 * 128u + ((gran ^ (row128 & 7u)) << 4);
}

DINLINE uint32_t smem_u32(const void* p) {
    uint32_t r;
    asm("{ .reg .u64 t; cvta.to.shared.u64 t, %1; cvt.u32.u64 %0, t; }" : "=r"(r) : "l"(p));
    return r;
}

DINLINE void cp_async16(uint32_t saddr, const void* gaddr) {
    asm volatile("cp.async.cg.shared.global [%0], [%1], 16;" :: "r"(saddr), "l"(gaddr) : "memory");
}
DINLINE void cp_commit() { asm volatile("cp.async.commit_group;" ::: "memory"); }
DINLINE void cp_wait2() { asm volatile("cp.async.wait_group 2;" ::: "memory"); }

#define LDSM4(r, addr)                                                         \
    asm volatile("ldmatrix.sync.aligned.m8n8.x4.shared.b16 {%0,%1,%2,%3}, [%4];" \
                 : "=r"((r)[0]), "=r"((r)[1]), "=r"((r)[2]), "=r"((r)[3])      \
                 : "r"(addr))

DINLINE void mma_s8(uint32_t* c, const uint32_t* a, uint32_t b0, uint32_t b1) {
    asm volatile(
        "mma.sync.aligned.m16n8k32.row.col.s32.s8.s8.s32 "
        "{%0,%1,%2,%3}, {%4,%5,%6,%7}, {%8,%9}, {%0,%1,%2,%3};"
        : "+r"(c[0]), "+r"(c[1]), "+r"(c[2]), "+r"(c[3])
        : "r"(a[0]), "r"(a[1]), "r"(a[2]), "r"(a[3]), "r"(b0), "r"(b1));
}

DINLINE int q8(int v, float s) {
    int q = __float2int_rn((float)v * s);   // RNE matches jnp.round
    return q < -128 ? -128 : (q > 127 ? 127 : q);
}

// Auto-detect element storage: small int bit-pattern => int32 storage; else
// interpret the bits as float32 and round-to-nearest-even.
DINLINE uint32_t cvt_b(uint32_t bits) {
    int v = (int)bits;
    if (v < -128 || v > 127) v = __float2int_rn(__int_as_float(bits));
    v = v < -128 ? -128 : (v > 127 ? 127 : v);
    return (uint32_t)v & 0xFFu;
}

// ============================================================================
// x convert: 32-bit-stored values -> g_x8 int8 (same layout [M,K])
// ============================================================================
__global__ void __launch_bounds__(256) x_convert_kernel(const uint32_t* __restrict__ xin) {
    const size_t base = ((size_t)blockIdx.x * 256 + threadIdx.x) * 16;
    alignas(16) uint8_t o[16];
#pragma unroll
    for (int i = 0; i < 16; i += 4) {
        const uint4 v = *reinterpret_cast<const uint4*>(xin + base + i);
        o[i + 0] = (uint8_t)cvt_b(v.x);
        o[i + 1] = (uint8_t)cvt_b(v.y);
        o[i + 2] = (uint8_t)cvt_b(v.z);
        o[i + 3] = (uint8_t)cvt_b(v.w);
    }
    *reinterpret_cast<uint4*>(g_x8 + base) = *reinterpret_cast<const uint4*>(o);
}

// ============================================================================
// Weight convert + transpose: w[K,N] (N-contig, 32-bit stored) -> g_wT[N,K] int8
// ============================================================================
__global__ void __launch_bounds__(256) w_convert_transpose(const uint32_t* __restrict__ w) {
    __shared__ uint8_t t[64][65];
    const int tid = threadIdx.x;
    const int n0 = blockIdx.x * 64;
    const int k0 = blockIdx.y * 64;

    const int r = tid >> 2;
    const int cseg = (tid & 3) * 16;
    const uint32_t* src = w + (size_t)(k0 + r) * N_TOTAL + n0 + cseg;
#pragma unroll
    for (int i = 0; i < 16; i += 4) {
        const uint4 v = *reinterpret_cast<const uint4*>(src + i);
        t[r][cseg + i + 0] = (uint8_t)cvt_b(v.x);
        t[r][cseg + i + 1] = (uint8_t)cvt_b(v.y);
        t[r][cseg + i + 2] = (uint8_t)cvt_b(v.z);
        t[r][cseg + i + 3] = (uint8_t)cvt_b(v.w);
    }
    __syncthreads();

    const int n = tid >> 2;
    const int kseg = (tid & 3) * 16;
    alignas(16) uint8_t o[16];
#pragma unroll
    for (int j = 0; j < 16; ++j) o[j] = t[kseg + j][n];
    *reinterpret_cast<uint4*>(g_wT + (size_t)(n0 + n) * K_TOTAL + k0 + kseg) =
        *reinterpret_cast<const uint4*>(o);
}

// ============================================================================
// Hybrid GEMM kernel: tensor warps + dp4a warps
// ============================================================================
__global__ void __launch_bounds__(NTHREADS, 1)
w8a8_gemm_kernel(const float* __restrict__ ascale,
                 const float* __restrict__ bscale,
                 float* __restrict__ out) {
    extern __shared__ __align__(1024) uint8_t smem_raw[];
    const uint32_t smem = smem_u32(smem_raw);
    const int t = threadIdx.x;
    const int lane = t & 31;
    const int warp = t >> 5;

    // --- M-grouped raster: W tiles stay L2-resident while A streams ---
    const int bid = blockIdx.x;
    const int group_sz = GROUP_M * NUM_N;
    const int gid = bid / group_sz;
    const int within = bid - gid * group_sz;
    const int pid_m = gid * GROUP_M + (within % GROUP_M);
    const int pid_n = within / GROUP_M;
    const int m0 = pid_m * BM;
    const int n0 = pid_n * BN;

    // --- producers: 3 x 16B granules per thread per stage (512+1024 granules) ---
    uint32_t aS; const uint8_t* aG;
    {
        const int m = t >> 2, k16 = t & 3;
        aS = smem + swz_addr(m >> 1, (m & 1) * 4 + k16);
        aG = g_x8 + (size_t)(m0 + m) * K_TOTAL + k16 * 16;
    }
    uint32_t bS[2]; const uint8_t* bG[2];
#pragma unroll
    for (int i = 0; i < 2; ++i) {
        const int q = t + i * NTHREADS;            // 0..1023
        const int n = q >> 2, k16 = q & 3;
        bS[i] = smem + A_BYTES + swz_addr(n >> 1, (n & 1) * 4 + k16);
        bG[i] = g_wT + (size_t)(n0 + n) * K_TOTAL + k16 * 16;
    }

    auto load_stage = [&](int s, int chunk) {
        const uint32_t so = s * STAGE_BYTES;
        const size_t ko = (size_t)chunk * BK;
        cp_async16(aS + so, aG + ko);
#pragma unroll
        for (int i = 0; i < 2; ++i) cp_async16(bS[i] + so, bG[i] + ko);
    };

    const float scl = ascale[0] * bscale[0];

    // --- prologue ---
#pragma unroll
    for (int s = 0; s < STAGES - 1; ++s) { load_stage(s, s); cp_commit(); }

    if (warp < 8) {
        // ================= tensor engine: cols [0, 160) =================
        const int wm = warp >> 2;   // 0..1 (64 rows)
        const int wn = warp & 3;    // 0..3 (40 cols each)

        // A x4 (PTX ISA a0..a3): m0=r0-7 klo, m1=r8-15 klo, m2=r0-7 khi, m3=r8-15 khi
        uint32_t aOff, bOff;
        {
            const int mlocal = ((lane >> 3) & 1) * 8 + (lane & 7);
            const int k16a = lane >> 4;
            const int am = wm * 64 + mlocal;
            aOff = swz_addr(am >> 1, (am & 1) * 4 + k16a);
            const int j = lane >> 3;
            const int nlocal = (j >> 1) * 8 + (lane & 7);
            const int k16b = j & 1;
            const int bn = wn * 40 + nlocal;
            bOff = A_BYTES + swz_addr(bn >> 1, (bn & 1) * 4 + k16b);
        }

        uint32_t acc[4][5][4];
#pragma unroll
        for (int mt = 0; mt < 4; ++mt)
#pragma unroll
            for (int nt = 0; nt < 5; ++nt)
#pragma unroll
                for (int r = 0; r < 4; ++r) acc[mt][nt][r] = 0;

        for (int c = 0; c < KCHUNKS; ++c) {
            cp_wait2();
            __syncthreads();
            if (c + STAGES - 1 < KCHUNKS)
                load_stage((c + STAGES - 1) & (STAGES - 1), c + STAGES - 1);
            cp_commit();

            const uint32_t so = (uint32_t)(c & (STAGES - 1)) * STAGE_BYTES;
#pragma unroll
            for (int kp = 0; kp < 2; ++kp) {
                const uint32_t kx = (uint32_t)kp << 5;
                uint32_t av[4][4];
#pragma unroll
                for (int mt = 0; mt < 4; ++mt) {
                    const uint32_t ad = smem + ((aOff + so + mt * 1024u) ^ kx);
                    LDSM4(av[mt], ad);
                }
                uint32_t bv[3][4];
#pragma unroll
                for (int nt2 = 0; nt2 < 3; ++nt2) {
                    const uint32_t bd = smem + ((bOff + so + nt2 * 1024u) ^ kx);
                    LDSM4(bv[nt2], bd);
                }
#pragma unroll
                for (int mt = 0; mt < 4; ++mt)
#pragma unroll
                    for (int nt = 0; nt < 5; ++nt) {
                        const uint32_t* bp = &bv[nt >> 1][(nt & 1) * 2];
                        mma_s8(acc[mt][nt], av[mt], bp[0], bp[1]);
                    }
            }
        }

        // epilogue (tensor)
#pragma unroll
        for (int mt = 0; mt < 4; ++mt) {
#pragma unroll
            for (int nt = 0; nt < 5; ++nt) {
                const int row = m0 + wm * 64 + mt * 16 + (lane >> 2);
                const int col = n0 + wn * 40 + nt * 8 + 2 * (lane & 3);
                const int* a4 = reinterpret_cast<const int*>(acc[mt][nt]);
                float2 v0, v1;
                v0.x = (float)q8(a4[0], scl);
                v0.y = (float)q8(a4[1], scl);
                v1.x = (float)q8(a4[2], scl);
                v1.y = (float)q8(a4[3], scl);
                *reinterpret_cast<float2*>(out + (size_t)row * N_TOTAL + col) = v0;
                *reinterpret_cast<float2*>(out + (size_t)(row + 8) * N_TOTAL + col) = v1;
            }
        }
    } else {
        // ================= dp4a engine: cols [160, 256) =================
        const int dw = warp - 8;
        const int r0 = (dw & 3) * 32;               // 4 row-quads of 32
        const int c0 = TENSOR_N + (dw >> 2) * 48;   // 2 col-halves of 48
        const int tr = lane >> 3;                   // 0..3 -> 8-row group
        const int tc = lane & 7;                    // 0..7 -> 6-col group

        uint32_t aoffs[8], boffs[6];
        uint32_t as3[8], bs3[6];
#pragma unroll
        for (int i = 0; i < 8; ++i) {
            const int r = r0 + tr * 8 + i;
            const uint32_t r128 = (uint32_t)r >> 1;
            const uint32_t s = r128 & 7u;
            const uint32_t gb = (uint32_t)(r & 1) * 4u;
            aoffs[i] = r128 * 128u + ((gb ^ (s & 4u)) << 4);
            as3[i] = s & 3u;
        }
#pragma unroll
        for (int j = 0; j < 6; ++j) {
            const int n = c0 + tc * 6 + j;
            const uint32_t n128 = (uint32_t)n >> 1;
            const uint32_t s = n128 & 7u;
            const uint32_t gb = (uint32_t)(n & 1) * 4u;
            boffs[j] = A_BYTES + n128 * 128u + ((gb ^ (s & 4u)) << 4);
            bs3[j] = s & 3u;
        }

        int accd[8][6];
#pragma unroll
        for (int i = 0; i < 8; ++i)
#pragma unroll
            for (int j = 0; j < 6; ++j) accd[i][j] = 0;

        for (int c = 0; c < KCHUNKS; ++c) {
            cp_wait2();
            __syncthreads();
            if (c + STAGES - 1 < KCHUNKS)
                load_stage((c + STAGES - 1) & (STAGES - 1), c + STAGES - 1);
            cp_commit();

            const uint32_t so = (uint32_t)(c & (STAGES - 1)) * STAGE_BYTES;
#pragma unroll
            for (int g = 0; g < 4; ++g) {   // logical 16B k-granule
                uint4 br[6];
#pragma unroll
                for (int j = 0; j < 6; ++j)
                    br[j] = *reinterpret_cast<const uint4*>(
                        smem_raw + so + boffs[j] + (((uint32_t)g ^ bs3[j]) << 4));
#pragma unroll
                for (int ih = 0; ih < 2; ++ih) {
                    uint4 ar[4];
#pragma unroll
                    for (int ii = 0; ii < 4; ++ii) {
                        const int i = ih * 4 + ii;
                        ar[ii] = *reinterpret_cast<const uint4*>(
                            smem_raw + so + aoffs[i] + (((uint32_t)g ^ as3[i]) << 4));
                    }
#pragma unroll
                    for (int ii = 0; ii < 4; ++ii)
#pragma unroll
                        for (int j = 0; j < 6; ++j) {
                            int& a = accd[ih * 4 + ii][j];
                            a = __dp4a((int)ar[ii].x, (int)br[j].x, a);
                            a = __dp4a((int)ar[ii].y, (int)br[j].y, a);
                            a = __dp4a((int)ar[ii].z, (int)br[j].z, a);
                            a = __dp4a((int)ar[ii].w, (int)br[j].w, a);
                        }
                }
            }
        }

        // epilogue (dp4a)
#pragma unroll
        for (int i = 0; i < 8; ++i) {
            const int row = m0 + r0 + tr * 8 + i;
            const int colb = n0 + c0 + tc * 6;
#pragma unroll
            for (int jp = 0; jp < 3; ++jp) {
                float2 v;
                v.x = (float)q8(accd[i][2 * jp + 0], scl);
                v.y = (float)q8(accd[i][2 * jp + 1], scl);
                *reinterpret_cast<float2*>(out + (size_t)row * N_TOTAL + colb + 2 * jp) = v;
            }
        }
    }
}

// ============================================================================
// Launch — identify inputs by element count (robust to metadata ordering)
// ============================================================================
extern "C" void kernel_launch(void* const* d_in, const int* in_sizes, int n_in,
                              void* d_out, int out_size) {
    (void)out_size;
    const uint32_t* x = nullptr;
    const uint32_t* w = nullptr;
    const float* s1 = nullptr;
    const float* s2 = nullptr;
    for (int i = 0; i < n_in; ++i) {
        const long sz = in_sizes[i];
        if (sz == (long)M_TOTAL * K_TOTAL) x = (const uint32_t*)d_in[i];
        else if (sz == (long)K_TOTAL * N_TOTAL) w = (const uint32_t*)d_in[i];
        else if (sz == 1) { if (!s1) s1 = (const float*)d_in[i]; else s2 = (const float*)d_in[i]; }
    }
    if (!x || !w || !s1 || !s2) return;

    cudaFuncSetAttribute(w8a8_gemm_kernel,
                         cudaFuncAttributeMaxDynamicSharedMemorySize, (int)SMEM_TOTAL);

    x_convert_kernel<<<(M_TOTAL * K_TOTAL) / (256 * 16), 256>>>(x);
    w_convert_transpose<<<dim3(N_TOTAL / 64, K_TOTAL / 64), 256>>>(w);
    w8a8_gemm_kernel<<<NUM_M * NUM_N, NTHREADS, SMEM_TOTAL>>>(s1, s2, (float*)d_out);
}